// round 8
// baseline (speedup 1.0000x reference)
#include <cuda_runtime.h>
#include <stdint.h>

// Problem constants (fixed-shape problem)
#define kB      8
#define kH      1024
#define kW      1536
#define kHW     (kH * kW)
#define kN      2048
#define kBorder 16
#define kXEnd   (kW - kBorder)   // 1520
#define kYEnd   (kH - kBorder)   // 1008
#define kCap    1600000          // per-batch fallback candidate capacity
#define kSCap   49152            // per-batch prefiltered capacity
#define kPreF   0x3E800000u      // 0.25f bits: prefilter bound on neur
#define kFB     4096             // fine buckets = key32 >> 18
#define kMCap   3072             // survivor capacity
#define kWBuf   64               // per-warp small-candidate staging
#define kGSel   16               // selection blocks per batch

// Scratch (device globals -- zero-initialized; tails restore zeros)
__device__ unsigned long long g_cand[(size_t)kB * kCap];    // fallback only
__device__ unsigned long long g_small[(size_t)kB * kSCap];
__device__ unsigned long long g_sorted[kB * kMCap];
__device__ unsigned int       g_fhist[kB * kFB];
__device__ unsigned int       g_bcur[kB * kFB];             // scatter counters
__device__ unsigned int       g_count[kB];                  // fallback only
__device__ unsigned int       g_scount[kB];
__device__ unsigned int       g_F[kB], g_M[kB];
__device__ int                g_flag[kB];

// ---------------------------------------------------------------------------
// Taylor 2x2 refinement + output write (row r)
__device__ __forceinline__ void taylor_write(const float* sb, unsigned long long v,
                                             unsigned r, float* out, int b) {
    unsigned idx = (unsigned)(v & 0x1FFFFFull);
    int y = (int)(idx / kW), x = (int)(idx % kW);
    int yc = min(max(y, 1), kH - 2);
    int xc = min(max(x, 1), kW - 2);
    const float* p = sb + (size_t)yc * kW + xc;
    float s00 = p[0];
    float sp0 = p[kW],      sm0 = p[-kW];
    float s0p = p[1],       s0m = p[-1];
    float spp = p[kW + 1],  spm = p[kW - 1];
    float smp = p[-kW + 1], smm = p[-kW - 1];
    float gy  = 0.5f * (sp0 - sm0);
    float gx  = 0.5f * (s0p - s0m);
    float hyy = sp0 - 2.0f * s00 + sm0;
    float hxx = s0p - 2.0f * s00 + s0m;
    float hxy = 0.25f * (spp - spm - smp + smm);
    float det = hyy * hxx - hxy * hxy;
    bool  sing = fabsf(det) > 1e-12f;
    float sd = sing ? det : 1.0f;
    float iy = -(hxx * gy - hxy * gx) / sd;
    float ix = -(hyy * gx - hxy * gy) / sd;
    if (!sing) { iy = 0.0f; ix = 0.0f; }
    iy = fminf(fmaxf(iy, -0.5f), 0.5f);
    ix = fminf(fmaxf(ix, -0.5f), 0.5f);
    float* o = out + ((size_t)b * kN + r) * 3;
    o[0] = (float)y + 0.5f + iy;
    o[1] = (float)x + 0.5f + ix;
    o[2] = __uint_as_float((unsigned)(v >> 21));
}

// ---------------------------------------------------------------------------
// Per-row NMS emit
__device__ __forceinline__ void nms_row(
    float4 Bc, float v0, float v1, float v2, float v3, float vel, float ver,
    int lane, int gx, int gy, int b,
    const float* nb, unsigned long long (&buf)[kWBuf], unsigned* s_cnt_w) {
    float vprev = __shfl_up_sync(0xffffffffu, v3, 1);
    if (lane == 0)  vprev = vel;
    float vnext = __shfl_down_sync(0xffffffffu, v0, 1);
    if (lane == 31) vnext = ver;

    bool c0 = (Bc.x >= fmaxf(vprev, fmaxf(v0, v1))) && (gx     < kXEnd);
    bool c1 = (Bc.y >= fmaxf(v0,    fmaxf(v1, v2))) && (gx + 1 < kXEnd);
    bool c2 = (Bc.z >= fmaxf(v1,    fmaxf(v2, v3))) && (gx + 2 < kXEnd);
    bool c3 = (Bc.w >= fmaxf(v2,    fmaxf(v3, vnext))) && (gx + 3 < kXEnd);
    if (c0 | c1 | c2 | c3) {
        float4 nv = *(const float4*)(nb + (size_t)gy * kW + gx);
        const float nvs[4] = {nv.x, nv.y, nv.z, nv.w};
        const bool  cf[4]  = {c0, c1, c2, c3};
        unsigned rowbase = (unsigned)(gy * kW + gx);
#pragma unroll
        for (int j = 0; j < 4; ++j) {
            if (cf[j]) {
                unsigned key32 = __float_as_uint(fmaxf(nvs[j], 0.0f));
                if (key32 < kPreF) {   // only small keys can reach top-kN
                    atomicAdd(&g_fhist[b * kFB + (key32 >> 18)], 1u);
                    unsigned long long key =
                        ((unsigned long long)key32 << 21) | (rowbase + j);
                    unsigned p = atomicAdd(s_cnt_w, 1u);
                    if (p < kWBuf) buf[p] = key;
                    else {
                        unsigned gp = atomicAdd(&g_scount[b], 1u);
                        if (gp < kSCap) g_small[(size_t)b * kSCap + gp] = key;
                    }
                }
            }
        }
    }
}

// ---------------------------------------------------------------------------
// K1: warp-rolling 3x3 local-max, pair-row pipeline. Warp = 128 px x 8 rows.
__global__ __launch_bounds__(256) void k_mask(const float* __restrict__ in0,
                                              const float* __restrict__ in1) {
    __shared__ unsigned long long s_buf[8][kWBuf];
    __shared__ unsigned s_cnt[8];

    const int tid  = threadIdx.x;
    const int w    = tid >> 5;
    const int lane = tid & 31;
    if (lane == 0) s_cnt[w] = 0;

    int neg = (in0[lane] < 0.f) | (in0[32 + lane] < 0.f) |
              (in0[64 + lane] < 0.f) | (in0[96 + lane] < 0.f);
    unsigned swapm = __ballot_sync(0xffffffffu, neg);
    const float* score = swapm ? in0 : in1;
    const float* neur  = swapm ? in1 : in0;
    __syncwarp();

    const int b  = blockIdx.z;
    const int x0 = kBorder + blockIdx.x * 128;
    const int ys = kBorder + (blockIdx.y * 8 + w) * 8;
    const int gx = x0 + lane * 4;
    const bool active = (ys < kYEnd);
    const bool ld_ok = active && (gx + 4 <= kW);
    const bool ledge = active && (lane == 0);
    const bool redge = active && (lane == 31) && (x0 + 128 < kW);
    const float* sb = score + (size_t)b * kHW;
    const float* nb = neur  + (size_t)b * kHW;

    if (active) {
        const float4 z4 = make_float4(0.f, 0.f, 0.f, 0.f);
        float4 A  = ld_ok ? *(const float4*)(sb + (size_t)(ys - 1) * kW + gx) : z4;
        float4 Bv = ld_ok ? *(const float4*)(sb + (size_t)ys * kW + gx)       : z4;
        float la = 0.f, lb = 0.f, ra = 0.f, rb = 0.f;
        if (ledge) { la = sb[(size_t)(ys - 1) * kW + x0 - 1];
                     lb = sb[(size_t)ys * kW + x0 - 1]; }
        if (redge) { ra = sb[(size_t)(ys - 1) * kW + x0 + 128];
                     rb = sb[(size_t)ys * kW + x0 + 128]; }

#pragma unroll
        for (int i = 0; i < 8; i += 2) {
            const int gy = ys + i;
            float4 C = ld_ok ? *(const float4*)(sb + (size_t)(gy + 1) * kW + gx) : z4;
            float4 D = ld_ok ? *(const float4*)(sb + (size_t)(gy + 2) * kW + gx) : z4;
            float lc = 0.f, rc = 0.f, ld = 0.f, rd = 0.f;
            if (ledge) { lc = sb[(size_t)(gy + 1) * kW + x0 - 1];
                         ld = sb[(size_t)(gy + 2) * kW + x0 - 1]; }
            if (redge) { rc = sb[(size_t)(gy + 1) * kW + x0 + 128];
                         rd = sb[(size_t)(gy + 2) * kW + x0 + 128]; }
            {
                float v0 = fmaxf(fmaxf(A.x, Bv.x), C.x);
                float v1 = fmaxf(fmaxf(A.y, Bv.y), C.y);
                float v2 = fmaxf(fmaxf(A.z, Bv.z), C.z);
                float v3 = fmaxf(fmaxf(A.w, Bv.w), C.w);
                float vel = fmaxf(fmaxf(la, lb), lc);
                float ver = fmaxf(fmaxf(ra, rb), rc);
                nms_row(Bv, v0, v1, v2, v3, vel, ver, lane, gx, gy, b,
                        nb, s_buf[w], &s_cnt[w]);
            }
            {
                float v0 = fmaxf(fmaxf(Bv.x, C.x), D.x);
                float v1 = fmaxf(fmaxf(Bv.y, C.y), D.y);
                float v2 = fmaxf(fmaxf(Bv.z, C.z), D.z);
                float v3 = fmaxf(fmaxf(Bv.w, C.w), D.w);
                float vel = fmaxf(fmaxf(lb, lc), ld);
                float ver = fmaxf(fmaxf(rb, rc), rd);
                nms_row(C, v0, v1, v2, v3, vel, ver, lane, gx, gy + 1, b,
                        nb, s_buf[w], &s_cnt[w]);
            }
            A = C; Bv = D; la = lc; lb = ld; ra = rc; rb = rd;
        }
    }

    __syncwarp();
    unsigned n = min(s_cnt[w], (unsigned)kWBuf);
    unsigned base = 0;
    if (lane == 0 && n) base = atomicAdd(&g_scount[b], n);
    base = __shfl_sync(0xffffffffu, base, 0);
    for (unsigned i = lane; i < n; i += 32) {
        unsigned sp = base + i;
        if (sp < kSCap) g_small[(size_t)b * kSCap + sp] = s_buf[w][i];
    }
}

// ---------------------------------------------------------------------------
// K2a: per-batch: scan fine hist -> F, M; init scatter counters to exclusive
// bucket starts; zero hist (merged reset); publish flag.
__global__ __launch_bounds__(1024) void k_thresh() {
    __shared__ unsigned s_warp[32];
    __shared__ unsigned sF, sMF, sT;
    const int tid = threadIdx.x;
    const int b   = blockIdx.x;
    if (tid == 0) { sF = kFB - 1; sMF = 0; sT = 0; }
    __syncthreads();

    unsigned f0, f1, f2, f3;
    {
        int o = b * kFB + tid * 4;
        f0 = g_fhist[o]; f1 = g_fhist[o + 1]; f2 = g_fhist[o + 2]; f3 = g_fhist[o + 3];
        g_fhist[o] = 0; g_fhist[o + 1] = 0; g_fhist[o + 2] = 0; g_fhist[o + 3] = 0;
    }
    unsigned tsum = f0 + f1 + f2 + f3;
    unsigned tincl = tsum;
#pragma unroll
    for (int d = 1; d < 32; d <<= 1) {
        unsigned v = __shfl_up_sync(~0u, tincl, d);
        if ((tid & 31) >= d) tincl += v;
    }
    if ((tid & 31) == 31) s_warp[tid >> 5] = tincl;
    __syncthreads();
    if (tid < 32) {
        unsigned ww = s_warp[tid];
#pragma unroll
        for (int d = 1; d < 32; d <<= 1) {
            unsigned v = __shfl_up_sync(~0u, ww, d);
            if (tid >= d) ww += v;
        }
        s_warp[tid] = ww;
    }
    __syncthreads();
    unsigned wex   = (tid >= 32) ? s_warp[(tid >> 5) - 1] : 0u;
    unsigned texcl = tincl - tsum + wex;
    unsigned iend  = texcl + tsum;
    if (tid == 1023) sT = iend;
    if (texcl < (unsigned)kN && iend >= (unsigned)kN) {
        unsigned cum = texcl;
        unsigned fj[4] = {f0, f1, f2, f3};
#pragma unroll
        for (int j = 0; j < 4; ++j) {
            cum += fj[j];
            if (cum >= (unsigned)kN) { sF = tid * 4 + j; sMF = cum; break; }
        }
    }
    // scatter counters = exclusive starts
    {
        int o = b * kFB + tid * 4;
        g_bcur[o]     = texcl;
        g_bcur[o + 1] = texcl + f0;
        g_bcur[o + 2] = texcl + f0 + f1;
        g_bcur[o + 3] = texcl + f0 + f1 + f2;
    }
    __syncthreads();
    if (tid == 0) {
        unsigned scnt = g_scount[b];
        unsigned M = sMF ? sMF : sT;
        int flag = 0;
        if (scnt < (unsigned)kN || scnt > (unsigned)kSCap) flag = 1;
        else if (M > (unsigned)kMCap) flag = 2;
        g_F[b] = sF; g_M[b] = M; g_flag[b] = flag;
    }
}

// ---------------------------------------------------------------------------
// K2b: scatter survivors (bucket <= F) into g_sorted grouped by bucket.
__global__ __launch_bounds__(256) void k_scatter() {
    const int b = blockIdx.y;
    if (g_flag[b]) return;
    const unsigned F   = g_F[b];
    const unsigned cnt = g_scount[b];
    const unsigned long long* src = g_small + (size_t)b * kSCap;
    for (unsigned i = blockIdx.x * 256u + threadIdx.x; i < cnt; i += kGSel * 256u) {
        unsigned long long v = src[i];
        unsigned f = (unsigned)(v >> 39);
        if (f <= F) {
            unsigned p = atomicAdd(&g_bcur[b * kFB + f], 1u);
            g_sorted[b * kMCap + p] = v;   // p < M <= kMCap by construction
        }
    }
}

// ---------------------------------------------------------------------------
// K2c: rank + Taylor + write. Main path: all blocks cache grouped keys in
// smem, binary-search bucket region, exact rank. Fallback: block 0 exact.
__global__ __launch_bounds__(256) void k_rank(const float* __restrict__ in0,
                                              const float* __restrict__ in1,
                                              float* __restrict__ out) {
    __shared__ unsigned long long s_keys[kMCap];   // 24 KB
    __shared__ unsigned           s_fb[kFB];       // 16 KB (fallback only)
    __shared__ unsigned           s_w8[8];
    __shared__ unsigned sF2, sMF2, sT2;

    const int tid = threadIdx.x;
    const int g   = blockIdx.x;
    const int b   = blockIdx.y;
    const int flag = g_flag[b];

    int neg = (in0[tid & 127] < 0.0f) ? 1 : 0;
    unsigned swapm = __ballot_sync(0xffffffffu, neg);   // lanes sample 128 vals
    // (tid&127 covers 0..127 across warps; any warp seeing a negative -> swap)
    __shared__ int s_swap;
    if (tid == 0) s_swap = 0;
    __syncthreads();
    if (__popc(swapm) && (tid & 31) == 0) atomicOr(&s_swap, 1);
    __syncthreads();
    const float* score = s_swap ? in0 : in1;
    const float* neur  = s_swap ? in1 : in0;
    const float* sb  = score + (size_t)b * kHW;
    const float* nbp = neur  + (size_t)b * kHW;

    if (flag == 0) {
        const unsigned M = g_M[b];
        for (unsigned i = tid; i < M; i += 256)
            s_keys[i] = g_sorted[b * kMCap + i];
        __syncthreads();
        for (unsigned p = g * 256u + tid; p < M; p += kGSel * 256u) {
            unsigned long long v = s_keys[p];
            unsigned f = (unsigned)(v >> 39);
            // binary search: first index with bucket >= f (array bucket-sorted)
            unsigned lo = 0, hi = M;
            while (lo < hi) {
                unsigned mid = (lo + hi) >> 1;
                if ((unsigned)(s_keys[mid] >> 39) < f) lo = mid + 1; else hi = mid;
            }
            unsigned r = lo;
            for (unsigned q = lo; q < M && (unsigned)(s_keys[q] >> 39) == f; ++q)
                r += (s_keys[q] < v) ? 1u : 0u;
            if (r < (unsigned)kN) taylor_write(sb, v, r, out, b);
        }
        __syncthreads();
        if (tid == 0) { g_scount[b] = 0; g_count[b] = 0; }
        return;
    }

    // ================= exact fallback (never expected) =================
    if (g != 0) return;

    const unsigned long long* src;
    unsigned cnt;
    if (flag == 1) {
        // re-scan image, collect ALL extrema into g_cand
        for (unsigned i = tid; i < 1504u * 992u; i += 256u) {
            int y = kBorder + (int)(i / 1504u);
            int x = kBorder + (int)(i % 1504u);
            const float* p = sb + (size_t)y * kW + x;
            float c = p[0];
            float mx = fmaxf(fmaxf(fmaxf(p[-kW - 1], p[-kW]), fmaxf(p[-kW + 1], p[-1])),
                             fmaxf(fmaxf(p[1], p[kW - 1]), fmaxf(p[kW], p[kW + 1])));
            if (c >= mx) {
                unsigned key32 = __float_as_uint(fmaxf(nbp[(size_t)y * kW + x], 0.0f));
                unsigned long long key =
                    ((unsigned long long)key32 << 21) | (unsigned)(y * kW + x);
                unsigned gp = atomicAdd(&g_count[b], 1u);
                if (gp < kCap) g_cand[(size_t)b * kCap + gp] = key;
            }
        }
        __syncthreads();
        src = g_cand + (size_t)b * kCap;
        cnt = min(g_count[b], (unsigned)kCap);
    } else {
        src = g_small + (size_t)b * kSCap;
        cnt = min(g_scount[b], (unsigned)kSCap);
    }

    // build fine hist in shared
    for (int j = tid; j < kFB; j += 256) s_fb[j] = 0;
    if (tid == 0) { sF2 = kFB - 1; sMF2 = 0; sT2 = 0; }
    __syncthreads();
    for (unsigned i = tid; i < cnt; i += 256u)
        atomicAdd(&s_fb[min((unsigned)(src[i] >> 39), (unsigned)(kFB - 1))], 1u);
    __syncthreads();

    // scan 4096 buckets with 256 threads (16 each)
    unsigned lh[16], local = 0;
    const int base = tid * 16;
#pragma unroll
    for (int j = 0; j < 16; ++j) { lh[j] = s_fb[base + j]; local += lh[j]; }
    unsigned incl = local;
#pragma unroll
    for (int d = 1; d < 32; d <<= 1) {
        unsigned v = __shfl_up_sync(~0u, incl, d);
        if ((tid & 31) >= d) incl += v;
    }
    if ((tid & 31) == 31) s_w8[tid >> 5] = incl;
    __syncthreads();
    if (tid == 0) {
        unsigned run = 0;
#pragma unroll
        for (int k = 0; k < 8; ++k) { unsigned t = s_w8[k]; s_w8[k] = run; run += t; }
        sT2 = run;
    }
    __syncthreads();
    unsigned texcl = incl - local + s_w8[tid >> 5];
    unsigned iend  = texcl + local;
    if (texcl < (unsigned)kN && iend >= (unsigned)kN) {
        unsigned cum = texcl;
#pragma unroll
        for (int j = 0; j < 16; ++j) {
            cum += lh[j];
            if (cum >= (unsigned)kN) { sF2 = base + j; sMF2 = cum; break; }
        }
    }
    {
        unsigned run = texcl;
#pragma unroll
        for (int j = 0; j < 16; ++j) { s_fb[base + j] = run; run += lh[j]; }
    }
    __syncthreads();
    const unsigned F = sF2;
    const unsigned M = sMF2 ? sMF2 : sT2;

    if (M <= (unsigned)kMCap) {
        for (unsigned i = tid; i < cnt; i += 256u) {
            unsigned long long v = src[i];
            unsigned f = min((unsigned)(v >> 39), (unsigned)(kFB - 1));
            if (f <= F) {
                unsigned p = atomicAdd(&s_fb[f], 1u);
                s_keys[p] = v;
            }
        }
        __syncthreads();
        for (unsigned p = tid; p < M; p += 256u) {
            unsigned long long v = s_keys[p];
            unsigned f = min((unsigned)(v >> 39), (unsigned)(kFB - 1));
            unsigned start = f ? s_fb[f - 1] : 0u;
            unsigned end   = s_fb[f];
            unsigned r = start;
            for (unsigned q = start; q < end; ++q) r += (s_keys[q] < v) ? 1u : 0u;
            if (r < (unsigned)kN) taylor_write(sb, v, r, out, b);
        }
    } else {
        for (unsigned i = tid; i < cnt; i += 256u) {
            unsigned long long v = src[i];
            if (min((unsigned)(v >> 39), (unsigned)(kFB - 1)) > F) continue;
            unsigned r = 0;
            for (unsigned q = 0; q < cnt; ++q) r += (src[q] < v) ? 1u : 0u;
            if (r < (unsigned)kN) taylor_write(sb, v, r, out, b);
        }
    }
    __syncthreads();
    if (tid == 0) { g_scount[b] = 0; g_count[b] = 0; }
}

// ---------------------------------------------------------------------------
extern "C" void kernel_launch(void* const* d_in, const int* in_sizes, int n_in,
                              void* d_out, int out_size) {
    const float* in0 = (const float*)d_in[0];
    const float* in1 = (const float*)d_in[1];
    float* out = (float*)d_out;

    dim3 gd(12, 16, kB);
    k_mask<<<gd, 256>>>(in0, in1);

    k_thresh<<<kB, 1024>>>();
    k_scatter<<<dim3(kGSel, kB), 256>>>();
    k_rank<<<dim3(kGSel, kB), 256>>>(in0, in1, out);
}

// round 9
// speedup vs baseline: 1.0484x; 1.0484x over previous
#include <cuda_runtime.h>
#include <stdint.h>

// Problem constants (fixed-shape problem)
#define kB      8
#define kH      1024
#define kW      1536
#define kHW     (kH * kW)
#define kN      2048
#define kBorder 16
#define kXEnd   (kW - kBorder)   // 1520
#define kYEnd   (kH - kBorder)   // 1008
#define kCap    1600000          // per-batch fallback candidate capacity
#define kSCap   49152            // per-batch prefiltered capacity
#define kPreF   0x3E800000u      // 0.25f bits: prefilter bound on neur
#define kFB     4096             // fine buckets = key32 >> 18
#define kMCap   3072             // survivor capacity
#define kWBuf   64               // per-warp small-candidate staging
#define kGSel   16               // selection blocks per batch

// Scratch (device globals -- zero-initialized; tails restore zeros)
__device__ unsigned long long g_cand[(size_t)kB * kCap];    // fallback only
__device__ unsigned long long g_small[(size_t)kB * kSCap];
__device__ unsigned long long g_sorted[kB * kMCap];
__device__ unsigned int       g_fhist[kB * kFB];
__device__ unsigned int       g_bcur[kB * kFB];             // scatter counters
__device__ unsigned int       g_count[kB];                  // fallback only
__device__ unsigned int       g_scount[kB];
__device__ unsigned int       g_F[kB], g_M[kB];
__device__ int                g_flag[kB];

// ---------------------------------------------------------------------------
// Taylor 2x2 refinement + output write (row r)
__device__ __forceinline__ void taylor_write(const float* sb, unsigned long long v,
                                             unsigned r, float* out, int b) {
    unsigned idx = (unsigned)(v & 0x1FFFFFull);
    int y = (int)(idx / kW), x = (int)(idx % kW);
    int yc = min(max(y, 1), kH - 2);
    int xc = min(max(x, 1), kW - 2);
    const float* p = sb + (size_t)yc * kW + xc;
    float s00 = p[0];
    float sp0 = p[kW],      sm0 = p[-kW];
    float s0p = p[1],       s0m = p[-1];
    float spp = p[kW + 1],  spm = p[kW - 1];
    float smp = p[-kW + 1], smm = p[-kW - 1];
    float gy  = 0.5f * (sp0 - sm0);
    float gx  = 0.5f * (s0p - s0m);
    float hyy = sp0 - 2.0f * s00 + sm0;
    float hxx = s0p - 2.0f * s00 + s0m;
    float hxy = 0.25f * (spp - spm - smp + smm);
    float det = hyy * hxx - hxy * hxy;
    bool  sing = fabsf(det) > 1e-12f;
    float sd = sing ? det : 1.0f;
    float iy = -(hxx * gy - hxy * gx) / sd;
    float ix = -(hyy * gx - hxy * gy) / sd;
    if (!sing) { iy = 0.0f; ix = 0.0f; }
    iy = fminf(fmaxf(iy, -0.5f), 0.5f);
    ix = fminf(fmaxf(ix, -0.5f), 0.5f);
    float* o = out + ((size_t)b * kN + r) * 3;
    o[0] = (float)y + 0.5f + iy;
    o[1] = (float)x + 0.5f + ix;
    o[2] = __uint_as_float((unsigned)(v >> 21));
}

// ---------------------------------------------------------------------------
// Per-row NMS emit
__device__ __forceinline__ void nms_row(
    float4 Bc, float v0, float v1, float v2, float v3, float vel, float ver,
    int lane, int gx, int gy, int b,
    const float* nb, unsigned long long (&buf)[kWBuf], unsigned* s_cnt_w) {
    float vprev = __shfl_up_sync(0xffffffffu, v3, 1);
    if (lane == 0)  vprev = vel;
    float vnext = __shfl_down_sync(0xffffffffu, v0, 1);
    if (lane == 31) vnext = ver;

    bool c0 = (Bc.x >= fmaxf(vprev, fmaxf(v0, v1))) && (gx     < kXEnd);
    bool c1 = (Bc.y >= fmaxf(v0,    fmaxf(v1, v2))) && (gx + 1 < kXEnd);
    bool c2 = (Bc.z >= fmaxf(v1,    fmaxf(v2, v3))) && (gx + 2 < kXEnd);
    bool c3 = (Bc.w >= fmaxf(v2,    fmaxf(v3, vnext))) && (gx + 3 < kXEnd);
    if (c0 | c1 | c2 | c3) {
        float4 nv = *(const float4*)(nb + (size_t)gy * kW + gx);
        const float nvs[4] = {nv.x, nv.y, nv.z, nv.w};
        const bool  cf[4]  = {c0, c1, c2, c3};
        unsigned rowbase = (unsigned)(gy * kW + gx);
#pragma unroll
        for (int j = 0; j < 4; ++j) {
            if (cf[j]) {
                unsigned key32 = __float_as_uint(fmaxf(nvs[j], 0.0f));
                if (key32 < kPreF) {   // only small keys can reach top-kN
                    atomicAdd(&g_fhist[b * kFB + (key32 >> 18)], 1u);
                    unsigned long long key =
                        ((unsigned long long)key32 << 21) | (rowbase + j);
                    unsigned p = atomicAdd(s_cnt_w, 1u);
                    if (p < kWBuf) buf[p] = key;
                    else {
                        unsigned gp = atomicAdd(&g_scount[b], 1u);
                        if (gp < kSCap) g_small[(size_t)b * kSCap + gp] = key;
                    }
                }
            }
        }
    }
}

// ---------------------------------------------------------------------------
// K1: warp-rolling 3x3 local-max, pair-row pipeline. Warp = 128 px x 8 rows.
__global__ __launch_bounds__(256) void k_mask(const float* __restrict__ in0,
                                              const float* __restrict__ in1) {
    __shared__ unsigned long long s_buf[8][kWBuf];
    __shared__ unsigned s_cnt[8];

    const int tid  = threadIdx.x;
    const int w    = tid >> 5;
    const int lane = tid & 31;
    if (lane == 0) s_cnt[w] = 0;

    int neg = (in0[lane] < 0.f) | (in0[32 + lane] < 0.f) |
              (in0[64 + lane] < 0.f) | (in0[96 + lane] < 0.f);
    unsigned swapm = __ballot_sync(0xffffffffu, neg);
    const float* score = swapm ? in0 : in1;
    const float* neur  = swapm ? in1 : in0;
    __syncwarp();

    const int b  = blockIdx.z;
    const int x0 = kBorder + blockIdx.x * 128;
    const int ys = kBorder + (blockIdx.y * 8 + w) * 8;
    const int gx = x0 + lane * 4;
    const bool active = (ys < kYEnd);
    const bool ld_ok = active && (gx + 4 <= kW);
    const bool ledge = active && (lane == 0);
    const bool redge = active && (lane == 31) && (x0 + 128 < kW);
    const float* sb = score + (size_t)b * kHW;
    const float* nb = neur  + (size_t)b * kHW;

    if (active) {
        const float4 z4 = make_float4(0.f, 0.f, 0.f, 0.f);
        float4 A  = ld_ok ? *(const float4*)(sb + (size_t)(ys - 1) * kW + gx) : z4;
        float4 Bv = ld_ok ? *(const float4*)(sb + (size_t)ys * kW + gx)       : z4;
        float la = 0.f, lb = 0.f, ra = 0.f, rb = 0.f;
        if (ledge) { la = sb[(size_t)(ys - 1) * kW + x0 - 1];
                     lb = sb[(size_t)ys * kW + x0 - 1]; }
        if (redge) { ra = sb[(size_t)(ys - 1) * kW + x0 + 128];
                     rb = sb[(size_t)ys * kW + x0 + 128]; }

#pragma unroll
        for (int i = 0; i < 8; i += 2) {
            const int gy = ys + i;
            float4 C = ld_ok ? *(const float4*)(sb + (size_t)(gy + 1) * kW + gx) : z4;
            float4 D = ld_ok ? *(const float4*)(sb + (size_t)(gy + 2) * kW + gx) : z4;
            float lc = 0.f, rc = 0.f, ld = 0.f, rd = 0.f;
            if (ledge) { lc = sb[(size_t)(gy + 1) * kW + x0 - 1];
                         ld = sb[(size_t)(gy + 2) * kW + x0 - 1]; }
            if (redge) { rc = sb[(size_t)(gy + 1) * kW + x0 + 128];
                         rd = sb[(size_t)(gy + 2) * kW + x0 + 128]; }
            {
                float v0 = fmaxf(fmaxf(A.x, Bv.x), C.x);
                float v1 = fmaxf(fmaxf(A.y, Bv.y), C.y);
                float v2 = fmaxf(fmaxf(A.z, Bv.z), C.z);
                float v3 = fmaxf(fmaxf(A.w, Bv.w), C.w);
                float vel = fmaxf(fmaxf(la, lb), lc);
                float ver = fmaxf(fmaxf(ra, rb), rc);
                nms_row(Bv, v0, v1, v2, v3, vel, ver, lane, gx, gy, b,
                        nb, s_buf[w], &s_cnt[w]);
            }
            {
                float v0 = fmaxf(fmaxf(Bv.x, C.x), D.x);
                float v1 = fmaxf(fmaxf(Bv.y, C.y), D.y);
                float v2 = fmaxf(fmaxf(Bv.z, C.z), D.z);
                float v3 = fmaxf(fmaxf(Bv.w, C.w), D.w);
                float vel = fmaxf(fmaxf(lb, lc), ld);
                float ver = fmaxf(fmaxf(rb, rc), rd);
                nms_row(C, v0, v1, v2, v3, vel, ver, lane, gx, gy + 1, b,
                        nb, s_buf[w], &s_cnt[w]);
            }
            A = C; Bv = D; la = lc; lb = ld; ra = rc; rb = rd;
        }
    }

    __syncwarp();
    unsigned n = min(s_cnt[w], (unsigned)kWBuf);
    unsigned base = 0;
    if (lane == 0 && n) base = atomicAdd(&g_scount[b], n);
    base = __shfl_sync(0xffffffffu, base, 0);
    for (unsigned i = lane; i < n; i += 32) {
        unsigned sp = base + i;
        if (sp < kSCap) g_small[(size_t)b * kSCap + sp] = s_buf[w][i];
    }
}

// ---------------------------------------------------------------------------
// K2a: per-batch: scan fine hist -> F, M; init scatter counters to exclusive
// bucket starts; zero hist (merged reset); publish flag.
__global__ __launch_bounds__(1024) void k_thresh() {
    __shared__ unsigned s_warp[32];
    __shared__ unsigned sF, sMF, sT;
    const int tid = threadIdx.x;
    const int b   = blockIdx.x;
    if (tid == 0) { sF = kFB - 1; sMF = 0; sT = 0; }
    __syncthreads();

    unsigned f0, f1, f2, f3;
    {
        int o = b * kFB + tid * 4;
        f0 = g_fhist[o]; f1 = g_fhist[o + 1]; f2 = g_fhist[o + 2]; f3 = g_fhist[o + 3];
        g_fhist[o] = 0; g_fhist[o + 1] = 0; g_fhist[o + 2] = 0; g_fhist[o + 3] = 0;
    }
    unsigned tsum = f0 + f1 + f2 + f3;
    unsigned tincl = tsum;
#pragma unroll
    for (int d = 1; d < 32; d <<= 1) {
        unsigned v = __shfl_up_sync(~0u, tincl, d);
        if ((tid & 31) >= d) tincl += v;
    }
    if ((tid & 31) == 31) s_warp[tid >> 5] = tincl;
    __syncthreads();
    if (tid < 32) {
        unsigned ww = s_warp[tid];
#pragma unroll
        for (int d = 1; d < 32; d <<= 1) {
            unsigned v = __shfl_up_sync(~0u, ww, d);
            if (tid >= d) ww += v;
        }
        s_warp[tid] = ww;
    }
    __syncthreads();
    unsigned wex   = (tid >= 32) ? s_warp[(tid >> 5) - 1] : 0u;
    unsigned texcl = tincl - tsum + wex;
    unsigned iend  = texcl + tsum;
    if (tid == 1023) sT = iend;
    if (texcl < (unsigned)kN && iend >= (unsigned)kN) {
        unsigned cum = texcl;
        unsigned fj[4] = {f0, f1, f2, f3};
#pragma unroll
        for (int j = 0; j < 4; ++j) {
            cum += fj[j];
            if (cum >= (unsigned)kN) { sF = tid * 4 + j; sMF = cum; break; }
        }
    }
    {
        int o = b * kFB + tid * 4;
        g_bcur[o]     = texcl;
        g_bcur[o + 1] = texcl + f0;
        g_bcur[o + 2] = texcl + f0 + f1;
        g_bcur[o + 3] = texcl + f0 + f1 + f2;
    }
    __syncthreads();
    if (tid == 0) {
        unsigned scnt = g_scount[b];
        unsigned M = sMF ? sMF : sT;
        int flag = 0;
        if (scnt < (unsigned)kN || scnt > (unsigned)kSCap) flag = 1;
        else if (M > (unsigned)kMCap) flag = 2;
        g_F[b] = sF; g_M[b] = M; g_flag[b] = flag;
    }
}

// ---------------------------------------------------------------------------
// K2b: scatter survivors (bucket <= F) into g_sorted grouped by bucket.
__global__ __launch_bounds__(256) void k_scatter() {
    const int b = blockIdx.y;
    if (g_flag[b]) return;
    const unsigned F   = g_F[b];
    const unsigned cnt = g_scount[b];
    const unsigned long long* src = g_small + (size_t)b * kSCap;
    for (unsigned i = blockIdx.x * 256u + threadIdx.x; i < cnt; i += kGSel * 256u) {
        unsigned long long v = src[i];
        unsigned f = (unsigned)(v >> 39);
        if (f <= F) {
            unsigned p = atomicAdd(&g_bcur[b * kFB + f], 1u);
            g_sorted[b * kMCap + p] = v;   // p < M <= kMCap by construction
        }
    }
}

// ---------------------------------------------------------------------------
// K2c: rank + Taylor + write; zero smem -> high occupancy, direct L2 reads.
// Post-scatter g_bcur[f] = end of bucket f; start = f ? g_bcur[f-1] : 0.
__global__ __launch_bounds__(256) void k_rank(const float* __restrict__ in0,
                                              const float* __restrict__ in1,
                                              float* __restrict__ out) {
    const int tid = threadIdx.x;
    const int b   = blockIdx.y;
    if (g_flag[b]) return;

    // input-order detection (warp-local, 128 samples)
    const int lane = tid & 31;
    int neg = (in0[lane] < 0.f) | (in0[32 + lane] < 0.f) |
              (in0[64 + lane] < 0.f) | (in0[96 + lane] < 0.f);
    unsigned swapm = __ballot_sync(0xffffffffu, neg);
    const float* score = swapm ? in0 : in1;
    const float* sb = score + (size_t)b * kHW;

    const unsigned M = g_M[b];
    const unsigned long long* srt = g_sorted + b * kMCap;
    const unsigned* bc = g_bcur + b * kFB;

    for (unsigned p = blockIdx.x * 256u + tid; p < M; p += kGSel * 256u) {
        unsigned long long v = srt[p];
        unsigned f = (unsigned)(v >> 39);
        unsigned start = f ? bc[f - 1] : 0u;
        unsigned end   = bc[f];
        unsigned r = start;
        for (unsigned q = start; q < end; ++q) r += (srt[q] < v) ? 1u : 0u;
        if (r < (unsigned)kN) taylor_write(sb, v, r, out, b);
    }
}

// ---------------------------------------------------------------------------
// K2d: exact fallback (never expected) + counter reset. Exits fast if ok.
__global__ __launch_bounds__(256) void k_fallback(const float* __restrict__ in0,
                                                  const float* __restrict__ in1,
                                                  float* __restrict__ out) {
    __shared__ unsigned long long s_keys[kMCap];   // 24 KB
    __shared__ unsigned           s_fb[kFB];       // 16 KB
    __shared__ unsigned           s_w8[8];
    __shared__ unsigned sF2, sMF2, sT2;

    const int tid = threadIdx.x;
    const int b   = blockIdx.x;
    const int flag = g_flag[b];

    if (flag == 0) {
        if (tid == 0) { g_scount[b] = 0; g_count[b] = 0; }
        return;
    }

    const int lane = tid & 31;
    int neg = (in0[lane] < 0.f) | (in0[32 + lane] < 0.f) |
              (in0[64 + lane] < 0.f) | (in0[96 + lane] < 0.f);
    unsigned swapm = __ballot_sync(0xffffffffu, neg);
    const float* score = swapm ? in0 : in1;
    const float* neur  = swapm ? in1 : in0;
    const float* sb  = score + (size_t)b * kHW;
    const float* nbp = neur  + (size_t)b * kHW;

    const unsigned long long* src;
    unsigned cnt;
    if (flag == 1) {
        for (unsigned i = tid; i < 1504u * 992u; i += 256u) {
            int y = kBorder + (int)(i / 1504u);
            int x = kBorder + (int)(i % 1504u);
            const float* p = sb + (size_t)y * kW + x;
            float c = p[0];
            float mx = fmaxf(fmaxf(fmaxf(p[-kW - 1], p[-kW]), fmaxf(p[-kW + 1], p[-1])),
                             fmaxf(fmaxf(p[1], p[kW - 1]), fmaxf(p[kW], p[kW + 1])));
            if (c >= mx) {
                unsigned key32 = __float_as_uint(fmaxf(nbp[(size_t)y * kW + x], 0.0f));
                unsigned long long key =
                    ((unsigned long long)key32 << 21) | (unsigned)(y * kW + x);
                unsigned gp = atomicAdd(&g_count[b], 1u);
                if (gp < kCap) g_cand[(size_t)b * kCap + gp] = key;
            }
        }
        __syncthreads();
        src = g_cand + (size_t)b * kCap;
        cnt = min(g_count[b], (unsigned)kCap);
    } else {
        src = g_small + (size_t)b * kSCap;
        cnt = min(g_scount[b], (unsigned)kSCap);
    }

    for (int j = tid; j < kFB; j += 256) s_fb[j] = 0;
    if (tid == 0) { sF2 = kFB - 1; sMF2 = 0; sT2 = 0; }
    __syncthreads();
    for (unsigned i = tid; i < cnt; i += 256u)
        atomicAdd(&s_fb[min((unsigned)(src[i] >> 39), (unsigned)(kFB - 1))], 1u);
    __syncthreads();

    unsigned lh[16], local = 0;
    const int base = tid * 16;
#pragma unroll
    for (int j = 0; j < 16; ++j) { lh[j] = s_fb[base + j]; local += lh[j]; }
    unsigned incl = local;
#pragma unroll
    for (int d = 1; d < 32; d <<= 1) {
        unsigned v = __shfl_up_sync(~0u, incl, d);
        if ((tid & 31) >= d) incl += v;
    }
    if ((tid & 31) == 31) s_w8[tid >> 5] = incl;
    __syncthreads();
    if (tid == 0) {
        unsigned run = 0;
#pragma unroll
        for (int k = 0; k < 8; ++k) { unsigned t = s_w8[k]; s_w8[k] = run; run += t; }
        sT2 = run;
    }
    __syncthreads();
    unsigned texcl = incl - local + s_w8[tid >> 5];
    unsigned iend  = texcl + local;
    if (texcl < (unsigned)kN && iend >= (unsigned)kN) {
        unsigned cum = texcl;
#pragma unroll
        for (int j = 0; j < 16; ++j) {
            cum += lh[j];
            if (cum >= (unsigned)kN) { sF2 = base + j; sMF2 = cum; break; }
        }
    }
    {
        unsigned run = texcl;
#pragma unroll
        for (int j = 0; j < 16; ++j) { s_fb[base + j] = run; run += lh[j]; }
    }
    __syncthreads();
    const unsigned F = sF2;
    const unsigned M = sMF2 ? sMF2 : sT2;

    if (M <= (unsigned)kMCap) {
        for (unsigned i = tid; i < cnt; i += 256u) {
            unsigned long long v = src[i];
            unsigned f = min((unsigned)(v >> 39), (unsigned)(kFB - 1));
            if (f <= F) {
                unsigned p = atomicAdd(&s_fb[f], 1u);
                s_keys[p] = v;
            }
        }
        __syncthreads();
        for (unsigned p = tid; p < M; p += 256u) {
            unsigned long long v = s_keys[p];
            unsigned f = min((unsigned)(v >> 39), (unsigned)(kFB - 1));
            unsigned start = f ? s_fb[f - 1] : 0u;
            unsigned end   = s_fb[f];
            unsigned r = start;
            for (unsigned q = start; q < end; ++q) r += (s_keys[q] < v) ? 1u : 0u;
            if (r < (unsigned)kN) taylor_write(sb, v, r, out, b);
        }
    } else {
        for (unsigned i = tid; i < cnt; i += 256u) {
            unsigned long long v = src[i];
            if (min((unsigned)(v >> 39), (unsigned)(kFB - 1)) > F) continue;
            unsigned r = 0;
            for (unsigned q = 0; q < cnt; ++q) r += (src[q] < v) ? 1u : 0u;
            if (r < (unsigned)kN) taylor_write(sb, v, r, out, b);
        }
    }
    __syncthreads();
    if (tid == 0) { g_scount[b] = 0; g_count[b] = 0; }
}

// ---------------------------------------------------------------------------
extern "C" void kernel_launch(void* const* d_in, const int* in_sizes, int n_in,
                              void* d_out, int out_size) {
    const float* in0 = (const float*)d_in[0];
    const float* in1 = (const float*)d_in[1];
    float* out = (float*)d_out;

    dim3 gd(12, 16, kB);
    k_mask<<<gd, 256>>>(in0, in1);

    k_thresh<<<kB, 1024>>>();
    k_scatter<<<dim3(kGSel, kB), 256>>>();
    k_rank<<<dim3(kGSel, kB), 256>>>(in0, in1, out);
    k_fallback<<<kB, 256>>>(in0, in1, out);
}